// round 10
// baseline (speedup 1.0000x reference)
#include <cuda_runtime.h>
#include <cuda_bf16.h>
#include <cstdint>
#include <cstddef>

#define HWSZ 40000
#define CD   128

// ---- scratch (static device globals; no runtime allocation) ----
// NOTE: these symbols are ONLY referenced from device code (host-side kernel
// args of __device__ symbols give host-shadow addresses — the round-7/8 bug).
__device__ float g_kv[4UL * 256 * 40000];        // conv output [n][o][pos] fp32
__device__ float g_tmp[2UL * 40000 * 128];       // q after head 0 (channels-last fp32)
__device__ __align__(16) __nv_bfloat16 g_xhi[4UL * 40000 * 128];   // X split-bf16
__device__ __align__(16) __nv_bfloat16 g_xlo[4UL * 40000 * 128];
__device__ __align__(16) __nv_bfloat16 g_whi[256 * 128];           // conv weight split
__device__ __align__(16) __nv_bfloat16 g_wlo[256 * 128];
__device__ __align__(16) __nv_bfloat16 g_pwhi[128 * 128];          // proj weight split
__device__ __align__(16) __nv_bfloat16 g_pwlo[128 * 128];
__device__ __align__(16) __nv_bfloat16 g_q2hi[2UL * 40000 * 128];  // q after head 1, split
__device__ __align__(16) __nv_bfloat16 g_q2lo[2UL * 40000 * 128];

// ===========================================================================
// PTX helpers
// ===========================================================================
__device__ __forceinline__ uint32_t smem_u32(const void* p) {
    uint32_t a;
    asm("{ .reg .u64 t; cvta.to.shared.u64 t, %1; cvt.u32.u64 %0, t; }"
        : "=r"(a) : "l"(p));
    return a;
}
#define LDMX4(r, addr)                                                        \
    asm volatile("ldmatrix.sync.aligned.m8n8.x4.shared.b16 {%0,%1,%2,%3}, [%4];" \
                 : "=r"((r)[0]), "=r"((r)[1]), "=r"((r)[2]), "=r"((r)[3])     \
                 : "r"(addr))
__device__ __forceinline__ void mma16816(float* d, const uint32_t* a,
                                         uint32_t b0, uint32_t b1) {
    asm volatile(
        "mma.sync.aligned.m16n8k16.row.col.f32.bf16.bf16.f32 "
        "{%0,%1,%2,%3}, {%4,%5,%6,%7}, {%8,%9}, {%0,%1,%2,%3};"
        : "+f"(d[0]), "+f"(d[1]), "+f"(d[2]), "+f"(d[3])
        : "r"(a[0]), "r"(a[1]), "r"(a[2]), "r"(a[3]), "r"(b0), "r"(b1));
}
#define CPA16(dst, src) \
    asm volatile("cp.async.cg.shared.global [%0], [%1], 16;" :: "r"(dst), "l"(src) : "memory")
#define CPA16Z(dst, src, sz) \
    asm volatile("cp.async.cg.shared.global [%0], [%1], 16, %2;" :: "r"(dst), "l"(src), "r"(sz) : "memory")
#define CPA_COMMIT() asm volatile("cp.async.commit_group;" ::: "memory")
#define CPA_WAIT0()  asm volatile("cp.async.wait_group 0;" ::: "memory")

// ===========================================================================
// split-bf16 conversion pre-pass. Destinations bound IN DEVICE CODE.
// ===========================================================================
__device__ __forceinline__ void split4(float4 v, uint2& hw, uint2& lw) {
    float f[4] = {v.x, v.y, v.z, v.w};
    uint32_t h2[2] = {0, 0}, l2[2] = {0, 0};
#pragma unroll
    for (int k = 0; k < 4; k++) {
        __nv_bfloat16 h = __float2bfloat16(f[k]);
        __nv_bfloat16 l = __float2bfloat16(f[k] - __bfloat162float(h));
        h2[k >> 1] |= (uint32_t)__bfloat16_as_ushort(h) << ((k & 1) * 16);
        l2[k >> 1] |= (uint32_t)__bfloat16_as_ushort(l) << ((k & 1) * 16);
    }
    hw = make_uint2(h2[0], h2[1]);
    lw = make_uint2(l2[0], l2[1]);
}

__global__ void __launch_bounds__(256) cvt_x_kernel(const float* __restrict__ x) {
    int i = blockIdx.x * blockDim.x + threadIdx.x;   // over 5,120,000 float4
    if (i >= 5120000) return;
    uint2 hw, lw;
    split4(((const float4*)x)[i], hw, lw);
    ((uint2*)g_xhi)[i] = hw;
    ((uint2*)g_xlo)[i] = lw;
}

__global__ void __launch_bounds__(256) cvt_w_kernel(const float* __restrict__ kvw,
                                                    const float* __restrict__ pw) {
    int i = blockIdx.x * blockDim.x + threadIdx.x;   // 8192 kvw + 4096 pw float4
    uint2 hw, lw;
    if (i < 8192) {
        split4(((const float4*)kvw)[i], hw, lw);
        ((uint2*)g_whi)[i] = hw;
        ((uint2*)g_wlo)[i] = lw;
    } else if (i < 12288) {
        int j = i - 8192;
        split4(((const float4*)pw)[j], hw, lw);
        ((uint2*)g_pwhi)[j] = hw;
        ((uint2*)g_pwlo)[j] = lw;
    }
}

// ===========================================================================
// GEMM tile layout: 128 rows x 128 bf16 cols, padded rows of 272B (136 elems).
// 272 mod 128 = 16 -> consecutive rows shift 4 banks: ldmatrix conflict-free.
// ===========================================================================
#define RSB  272                     // row stride bytes
#define TLB  (128 * RSB)             // one tile = 34816B
#define A_HI 0
#define A_LO (TLB)
#define B_HI (2 * TLB)
#define B_LO (3 * TLB)
#define SMT  (4 * TLB)               // 139264B dynamic smem

__device__ __forceinline__ void gemm128(uint32_t sb, int lane, int wm, int wn,
                                        float acc[4][4][4]) {
    const int aoff[3] = {A_HI, A_LO, A_HI};
    const int boff[3] = {B_HI, B_HI, B_LO};
    const int arow  = wm + (lane & 15);
    const int acolb = ((lane >> 4) << 3);
    const int brow  = wn + (lane & 7) + ((lane >> 4) << 3);
    const int bcolb = (((lane >> 3) & 1) << 3);
#pragma unroll
    for (int pass = 0; pass < 3; pass++) {
        uint32_t ab = sb + aoff[pass];
        uint32_t bb = sb + boff[pass];
#pragma unroll
        for (int ks = 0; ks < 8; ks++) {
            uint32_t a[4][4], b[2][4];
            int kc = ks * 16;
#pragma unroll
            for (int mt = 0; mt < 4; mt++)
                LDMX4(a[mt], ab + (uint32_t)(arow + mt * 16) * RSB
                               + (uint32_t)(kc + acolb) * 2);
#pragma unroll
            for (int np = 0; np < 2; np++)
                LDMX4(b[np], bb + (uint32_t)(brow + np * 16) * RSB
                               + (uint32_t)(kc + bcolb) * 2);
#pragma unroll
            for (int mt = 0; mt < 4; mt++)
#pragma unroll
                for (int nt = 0; nt < 4; nt++)
                    mma16816(acc[mt][nt], a[mt],
                             b[nt >> 1][(nt & 1) * 2], b[nt >> 1][(nt & 1) * 2 + 1]);
        }
    }
}

// ---------------------------------------------------------------------------
// conv 1x1: g_kv[n][o][p] = sum_c W[o][c] * X[n][p][c]
// grid (313 p-tiles, 2 o-blocks of 128, 4 n), 256 threads (8 warps: 2m x 4n).
// ---------------------------------------------------------------------------
__global__ void __launch_bounds__(256, 1) conv_hmma_kernel() {
    extern __shared__ char sm[];
    uint32_t sb = smem_u32(sm);
    const int tid = threadIdx.x, wid = tid >> 5, lane = tid & 31;
    const int p0 = blockIdx.x * 128;
    const int o0 = blockIdx.y * 128;
    const int n  = blockIdx.z;

#pragma unroll
    for (int i = 0; i < 16; i++) {
        int idx = tid + i * 256;
        int c16 = idx & 15, row = (idx >> 4) & 127, hl = idx >> 11;
        const __nv_bfloat16* src = (hl ? g_wlo : g_whi)
                                 + (size_t)(o0 + row) * CD + c16 * 8;
        uint32_t dst = sb + (hl ? A_LO : A_HI) + (uint32_t)row * RSB
                     + (uint32_t)c16 * 16;
        CPA16(dst, src);
    }
    const size_t xoff = (size_t)n * HWSZ * CD;
#pragma unroll
    for (int i = 0; i < 16; i++) {
        int idx = tid + i * 256;
        int c16 = idx & 15, row = (idx >> 4) & 127, hl = idx >> 11;
        int p = p0 + row;
        int sz = (p < HWSZ) ? 16 : 0;
        int pc = (p < HWSZ) ? p : 0;
        const __nv_bfloat16* src = (hl ? g_xlo : g_xhi)
                                 + xoff + (size_t)pc * CD + c16 * 8;
        uint32_t dst = sb + (hl ? B_LO : B_HI) + (uint32_t)row * RSB
                     + (uint32_t)c16 * 16;
        CPA16Z(dst, src, sz);
    }
    CPA_COMMIT();

    const int wm = (wid & 1) * 64, wn = (wid >> 1) * 32;
    float acc[4][4][4];
#pragma unroll
    for (int i = 0; i < 4; i++)
#pragma unroll
        for (int j = 0; j < 4; j++)
#pragma unroll
            for (int k = 0; k < 4; k++) acc[i][j][k] = 0.f;

    CPA_WAIT0();
    __syncthreads();
    gemm128(sb, lane, wm, wn, acc);

    const int g = lane >> 2, tg = lane & 3;
    float* O = g_kv + (size_t)n * 256 * HWSZ;
#pragma unroll
    for (int mt = 0; mt < 4; mt++) {
        int rr = o0 + wm + mt * 16 + g;
#pragma unroll
        for (int nt = 0; nt < 4; nt++) {
            int pp = p0 + wn + nt * 8 + tg * 2;
            if (pp < HWSZ) {
                *(float2*)&O[(size_t)rr * HWSZ + pp] =
                    make_float2(acc[mt][nt][0], acc[mt][nt][1]);
                *(float2*)&O[(size_t)(rr + 8) * HWSZ + pp] =
                    make_float2(acc[mt][nt][2], acc[mt][nt][3]);
            }
        }
    }
}

// ---------------------------------------------------------------------------
// projection: out[p][co] = sum_c q2[p][c] * Wp[co][c] + bias[co]
// grid (625 p-tiles of 128 over 80000), 256 threads.
// ---------------------------------------------------------------------------
__global__ void __launch_bounds__(256, 1)
proj_hmma_kernel(const float* __restrict__ bias, float* __restrict__ out) {
    extern __shared__ char sm[];
    uint32_t sb = smem_u32(sm);
    const int tid = threadIdx.x, wid = tid >> 5, lane = tid & 31;
    const int p0 = blockIdx.x * 128;

#pragma unroll
    for (int i = 0; i < 16; i++) {
        int idx = tid + i * 256;
        int c16 = idx & 15, row = (idx >> 4) & 127, hl = idx >> 11;
        const __nv_bfloat16* src = (hl ? g_q2lo : g_q2hi)
                                 + (size_t)(p0 + row) * CD + c16 * 8;
        uint32_t dst = sb + (hl ? A_LO : A_HI) + (uint32_t)row * RSB
                     + (uint32_t)c16 * 16;
        CPA16(dst, src);
    }
#pragma unroll
    for (int i = 0; i < 16; i++) {
        int idx = tid + i * 256;
        int c16 = idx & 15, row = (idx >> 4) & 127, hl = idx >> 11;
        const __nv_bfloat16* src = (hl ? g_pwlo : g_pwhi)
                                 + (size_t)row * CD + c16 * 8;
        uint32_t dst = sb + (hl ? B_LO : B_HI) + (uint32_t)row * RSB
                     + (uint32_t)c16 * 16;
        CPA16(dst, src);
    }
    CPA_COMMIT();

    const int wm = (wid & 1) * 64, wn = (wid >> 1) * 32;
    float acc[4][4][4];
#pragma unroll
    for (int i = 0; i < 4; i++)
#pragma unroll
        for (int j = 0; j < 4; j++)
#pragma unroll
            for (int k = 0; k < 4; k++) acc[i][j][k] = 0.f;

    CPA_WAIT0();
    __syncthreads();
    gemm128(sb, lane, wm, wn, acc);

    const int g = lane >> 2, tg = lane & 3;
#pragma unroll
    for (int mt = 0; mt < 4; mt++) {
        int p = p0 + wm + mt * 16 + g;
#pragma unroll
        for (int nt = 0; nt < 4; nt++) {
            int co = wn + nt * 8 + tg * 2;
            float b0 = bias[co], b1 = bias[co + 1];
            *(float2*)&out[(size_t)p * CD + co] =
                make_float2(acc[mt][nt][0] + b0, acc[mt][nt][1] + b1);
            *(float2*)&out[(size_t)(p + 8) * CD + co] =
                make_float2(acc[mt][nt][2] + b0, acc[mt][nt][3] + b1);
        }
    }
}

// ---------------------------------------------------------------------------
// Dilate attention, channel-paired, with STATIC index stream.
// Per thread, L(s) = l0 + 14400*s mod 25600 has period 16 and
// M(s) = Mt[s mod 16] + 25*(s/16), so full unroll makes every step's index
// math compile-time except one register read per array. Verified against the
// sequential recurrence: at step s the original loop reads tab[m0+s+w(s)]
// with w(s) = (l0 + 14400*s - L(s))/25600; for s=16q+t, w = w(t)+9q.
// ---------------------------------------------------------------------------
__global__ void __launch_bounds__(256, 2) attn_kernel(const float* __restrict__ qext,
                                                      int head, int dil, int stage) {
    __shared__ int2  tab[1800];
    __shared__ float st[64 * 129];
    const int tid = threadIdx.x;

    for (int m = tid; m < 1800; m += 256) {
        int c200 = m / 9;
        int kk = m - c200 * 9;
        int i = kk / 3;
        int j = kk - i * 3;
        int di = (i - 1) * dil;
        int dj = (j - 1) * dil;
        tab[m] = make_int2(c200 * 25600 + di * 128 + dj, (di << 16) | (dj & 0xFFFF));
    }
    __syncthreads();

    const float* qin = stage ? g_tmp : qext;

    const int b   = blockIdx.y;
    const int pl  = tid & 63;
    const int nh  = tid >> 6;
    const int pos0 = blockIdx.x * 64;
    const int pos  = pos0 + pl;

    const float* Qf = qin + (size_t)b * HWSZ * CD;
    const float* Kb = g_kv + ((size_t)(2 * b) * 256 + head * 128) * HWSZ;
    const float* Vb = g_kv + ((size_t)(2 * b + 1) * 256 + head * 128) * HWSZ;

    const int G0 = nh * 288 * 40000 + pos;
    const int m0 = G0 / 25600;
    const int l0 = G0 - m0 * 25600;

    // ---- precompute the 16-step cycle ----
    int Lv[16], lwv[16], lcv[16], Mt[16];
    {
        int L = l0, wrap = 0;
#pragma unroll
        for (int t = 0; t < 16; t++) {
            Lv[t]  = L;
            lwv[t] = L >> 7;
            lcv[t] = L & 127;
            Mt[t]  = m0 + t + wrap;
            L += 14400;
            if (L >= 25600) { L -= 25600; wrap++; }
        }
    }

    // ---- pass 1: scores (channels hd and hd+16 per step) ----
    float sc[9];
#pragma unroll
    for (int k = 0; k < 9; k++) sc[k] = 0.f;

    {
        float q1 = 0.f, q2 = 0.f;
#pragma unroll
        for (int s = 0; s < 144; s++) {
            const int hd = s / 9, kk = s - hd * 9;
            const int t = s & 15, qq = s >> 4;
            if (kk == 0) {
                q1 = Qf[(size_t)(nh * 32 + hd) * HWSZ + pos];
                q2 = Qf[(size_t)(nh * 32 + hd + 16) * HWSZ + pos];
            }
            int2 tv = tab[Mt[t] + 25 * qq];
            int di = tv.y >> 16;
            int dj = (int)(short)(tv.y & 0xFFFF);
            bool ok = ((unsigned)(lwv[t] + di) < 200u) && ((unsigned)(lcv[t] + dj) < 128u);
            int a = tv.x + Lv[t];
            float k1 = ok ? __ldg(&Kb[a]) : 0.f;
            float k2 = ok ? __ldg(&Kb[a + 640000]) : 0.f;
            sc[kk] = fmaf(q1, k1, sc[kk]);
            sc[kk] = fmaf(q2, k2, sc[kk]);
        }
    }

    // ---- softmax over 9 ----
    const float SCALE = 0.17677669529663687f;
    float mx = -1e30f;
#pragma unroll
    for (int k = 0; k < 9; k++) { sc[k] *= SCALE; mx = fmaxf(mx, sc[k]); }
    float sum = 0.f;
#pragma unroll
    for (int k = 0; k < 9; k++) { sc[k] = __expf(sc[k] - mx); sum += sc[k]; }
    float inv = 1.0f / sum;
#pragma unroll
    for (int k = 0; k < 9; k++) sc[k] *= inv;

    // ---- pass 2: outputs ----
    {
        float o1 = 0.f, o2 = 0.f;
#pragma unroll
        for (int s = 0; s < 144; s++) {
            const int hd = s / 9, kk = s - hd * 9;
            const int t = s & 15, qq = s >> 4;
            if (kk == 0) { o1 = 0.f; o2 = 0.f; }
            int2 tv = tab[Mt[t] + 25 * qq];
            int di = tv.y >> 16;
            int dj = (int)(short)(tv.y & 0xFFFF);
            bool ok = ((unsigned)(lwv[t] + di) < 200u) && ((unsigned)(lcv[t] + dj) < 128u);
            int a = tv.x + Lv[t];
            float v1 = ok ? __ldg(&Vb[a]) : 0.f;
            float v2 = ok ? __ldg(&Vb[a + 640000]) : 0.f;
            o1 = fmaf(sc[kk], v1, o1);
            o2 = fmaf(sc[kk], v2, o2);
            if (kk == 8) {
                st[pl * 129 + nh * 32 + hd]      = o1;
                st[pl * 129 + nh * 32 + hd + 16] = o2;
            }
        }
    }
    __syncthreads();

    const size_t obase = (size_t)b * HWSZ * CD + (size_t)pos0 * CD;
    if (stage) {
        __nv_bfloat16* Hh = g_q2hi + obase;
        __nv_bfloat16* Hl = g_q2lo + obase;
#pragma unroll
        for (int it = 0; it < 32; it++) {
            int f = tid + it * 256;
            int p = f >> 7, c = f & 127;
            float v = st[p * 129 + c];
            __nv_bfloat16 h = __float2bfloat16(v);
            Hh[f] = h;
            Hl[f] = __float2bfloat16(v - __bfloat162float(h));
        }
    } else {
        float* Ob = g_tmp + obase;
#pragma unroll
        for (int it = 0; it < 32; it++) {
            int f = tid + it * 256;
            int p = f >> 7, c = f & 127;
            Ob[f] = st[p * 129 + c];
        }
    }
}

extern "C" void kernel_launch(void* const* d_in, const int* in_sizes, int n_in,
                              void* d_out, int out_size) {
    const float* q   = (const float*)d_in[0];
    const float* x   = (const float*)d_in[1];
    const float* kvw = (const float*)d_in[2];
    const float* pw  = (const float*)d_in[3];
    const float* pb  = (const float*)d_in[4];
    float* out = (float*)d_out;

    cudaFuncSetAttribute(conv_hmma_kernel, cudaFuncAttributeMaxDynamicSharedMemorySize, SMT);
    cudaFuncSetAttribute(proj_hmma_kernel, cudaFuncAttributeMaxDynamicSharedMemorySize, SMT);

    cvt_x_kernel<<<20000, 256>>>(x);
    cvt_w_kernel<<<48, 256>>>(kvw, pw);

    conv_hmma_kernel<<<dim3(313, 2, 4), 256, SMT>>>();
    attn_kernel<<<dim3(625, 2), 256>>>(q, /*head=*/0, /*dil=*/1, /*stage=*/0);
    attn_kernel<<<dim3(625, 2), 256>>>(q, /*head=*/1, /*dil=*/2, /*stage=*/1);
    proj_hmma_kernel<<<625, 256, SMT>>>(pb, out);
}